// round 3
// baseline (speedup 1.0000x reference)
#include <cuda_runtime.h>

#define Bn 4
#define Hh 512
#define Ww 512
#define HW (Hh*Ww)
#define Ntot (Bn*HW)
#define EPSf 1e-8f
#define NITER 20
#define TILE 31        // owned interior per block
#define RGN 32         // computed region (TILE + 1 halo, = warp width)
#define NT 17          // ceil(512/31)
#define SP 33          // smem pitch in float2

// State in vector-packed device globals (no runtime alloc)
__device__ float4 g_cfg[Ntot];        // (rho, gx, gy, pad)
__device__ float2 g_u2[2][Ntot];      // (u0, u1)
__device__ float4 g_p4[2][Ntot];      // (p1x, p1y, p2x, p2y)

__global__ void init_kernel() {
    int i = blockIdx.x*blockDim.x + threadIdx.x;
    if (i < Ntot) {
        g_u2[0][i] = make_float2(0.f, 0.f);
        g_p4[0][i] = make_float4(0.f, 0.f, 0.f, 0.f);
    }
}

// cfg = (I1-I0, K_GRAD_x*I1, K_GRAD_y*I1) with zero padding
__global__ void pre_kernel(const float* __restrict__ x) {
    int i = blockIdx.x*blockDim.x + threadIdx.x;
    if (i >= Ntot) return;
    int b = i >> 18;
    int hw = i & (HW-1);
    int h = hw >> 9;
    int w = hw & (Ww-1);
    const float* I0 = x + (size_t)b*2*HW;
    const float* I1 = I0 + HW;

    auto at = [&](int dh, int dw) -> float {
        int hh = h+dh, ww = w+dw;
        if (hh < 0 || hh >= Hh || ww < 0 || ww >= Ww) return 0.f;
        return I1[hh*Ww + ww];
    };
    float a00=at(-1,-1), a01=at(-1,0), a02=at(-1,1);
    float a10=at( 0,-1),               a12=at( 0,1);
    float a20=at( 1,-1), a21=at( 1,0), a22=at( 1,1);
    float gx = (-a00 + a02 - 2.f*a10 + 2.f*a12 - a20 + a22) * (1.f/6.f);
    float gy = (-a00 - 2.f*a01 - a02 + a20 + 2.f*a21 + a22) * (1.f/6.f);
    g_cfg[i] = make_float4(I1[hw] - I0[hw], gx, gy, 0.f);
}

// One fused TV-L1 iteration. 32x32 region computed (u-update), 31x31 interior
// owned (u/p written). Register budget capped for 6 blocks/SM occupancy;
// p center is re-loaded in phase 2 (L1 hit) instead of held across the barrier.
__global__ __launch_bounds__(256, 6) void iter_kernel(int src,
    const float* __restrict__ lam_p, const float* __restrict__ tau_p,
    const float* __restrict__ theta_p,
    const float* __restrict__ wx, const float* __restrict__ wy)
{
    const float theta = theta_p[0];
    const float tl = theta * lam_p[0];
    const float rr = tau_p[0] / theta;
    const float wx0 = wx[0], wx1 = wx[1], wx2 = wx[2];
    const float wy0 = wy[0], wy1 = wy[1], wy2 = wy[2];

    const float2* __restrict__ u_in = g_u2[src];
    const float4* __restrict__ p_in = g_p4[src];
    float2* __restrict__ u_out = g_u2[src^1];
    float4* __restrict__ p_out = g_p4[src^1];

    const int tx = threadIdx.x & 31;
    const int ty = threadIdx.x >> 5;
    const int b  = blockIdx.z;
    const int h0 = blockIdx.y * TILE;
    const int w0 = blockIdx.x * TILE;
    const int w  = w0 + tx;
    const int base = b * HW;

    __shared__ float2 s_u[RGN*SP];

    // ---- Phase 1: u_new over the full 32x32 region (zero outside image) ----
    #pragma unroll
    for (int i = 0; i < 4; i++) {
        int lr = ty + i*8;
        int h = h0 + lr;
        float2 res = make_float2(0.f, 0.f);
        if (h < Hh && w < Ww) {
            int idx = base + h*Ww + w;
            float4 cfg = g_cfg[idx];
            float2 u = u_in[idx];
            float4 p = p_in[idx];
            float4 z4 = make_float4(0.f, 0.f, 0.f, 0.f);
            float4 pl = (w > 0)    ? p_in[idx-1]  : z4;
            float4 pr = (w < Ww-1) ? p_in[idx+1]  : z4;
            float4 pu = (h > 0)    ? p_in[idx-Ww] : z4;
            float4 pd = (h < Hh-1) ? p_in[idx+Ww] : z4;
            float gx = cfg.y, gy = cfg.z;
            float rho = cfg.x + gx*u.x + gy*u.y;
            float ng = gx*gx + gy*gy + EPSf;
            float th = tl * ng;
            float d0, d1;
            if (fabsf(rho) < th) {
                float inv = 1.0f / ng;
                d0 = rho*gx*inv; d1 = rho*gy*inv;
            } else {
                float s = (rho > 0.f) ? 1.f : ((rho < 0.f) ? -1.f : 0.f);
                d0 = tl*gx*s; d1 = tl*gy*s;
            }
            float div1 = wx0*pl.x + wx1*p.x + wx2*pr.x + wy0*pu.y + wy1*p.y + wy2*pd.y;
            float div2 = wx0*pl.z + wx1*p.z + wx2*pr.z + wy0*pu.w + wy1*p.w + wy2*pd.w;
            res.x = (u.x - d0) + theta*div1;
            res.y = (u.y - d1) + theta*div2;
        }
        s_u[lr*SP + tx] = res;
    }
    __syncthreads();

    // ---- Phase 2: p_new + writes on the 31x31 interior, from SMEM u_new ----
    if (tx < TILE && w < Ww) {
        #pragma unroll
        for (int i = 0; i < 4; i++) {
            int lr = ty + i*8;
            if (lr >= TILE) continue;
            int h = h0 + lr;
            if (h >= Hh) continue;
            int idx = base + h*Ww + w;
            float4 p = p_in[idx];            // L1 hit: same line as phase 1
            float2 c   = s_u[lr*SP + tx];
            float2 rgt = s_u[lr*SP + tx + 1];
            float2 dwn = s_u[(lr+1)*SP + tx];
            float gx0 = rgt.x - c.x, gy0 = dwn.x - c.x;
            float gx1 = rgt.y - c.y, gy1 = dwn.y - c.y;
            float i1 = 1.f / (1.f + rr*(fabsf(gx0) + fabsf(gy0)));
            float i2 = 1.f / (1.f + rr*(fabsf(gx1) + fabsf(gy1)));
            u_out[idx] = c;
            p_out[idx] = make_float4((p.x + rr*gx0)*i1,
                                     (p.y + rr*gy0)*i1,
                                     (p.z + rr*gx1)*i2,
                                     (p.w + rr*gy1)*i2);
        }
    }
}

// AvgPool2d(3, stride 1, pad 1, count_include_pad -> always /9), both channels
__global__ void avg_kernel(float* __restrict__ out) {
    int i = blockIdx.x*blockDim.x + threadIdx.x;
    if (i >= Ntot) return;
    int w = i & (Ww-1);
    int h = (i >> 9) & (Hh-1);
    int b = i >> 18;
    const float2* u = g_u2[0] + b*HW;   // final state is in buf 0 after 20 iters
    float sx = 0.f, sy = 0.f;
    #pragma unroll
    for (int dh = -1; dh <= 1; dh++) {
        int hh = h + dh;
        if (hh < 0 || hh >= Hh) continue;
        #pragma unroll
        for (int dw = -1; dw <= 1; dw++) {
            int ww = w + dw;
            if (ww < 0 || ww >= Ww) continue;
            float2 v = u[hh*Ww + ww];
            sx += v.x; sy += v.y;
        }
    }
    int o = b*2*HW + h*Ww + w;
    out[o]      = sx * (1.f/9.f);
    out[o + HW] = sy * (1.f/9.f);
}

extern "C" void kernel_launch(void* const* d_in, const int* in_sizes, int n_in,
                              void* d_out, int out_size) {
    const float* x     = (const float*)d_in[0];
    const float* lam   = (const float*)d_in[1];
    const float* tau   = (const float*)d_in[2];
    const float* theta = (const float*)d_in[3];
    const float* wx    = (const float*)d_in[4];
    const float* wy    = (const float*)d_in[5];
    float* out = (float*)d_out;

    init_kernel<<<(Ntot + 255)/256, 256>>>();
    pre_kernel<<<(Ntot + 255)/256, 256>>>(x);

    dim3 grid(NT, NT, Bn);   // 17 x 17 x 4 = 1156 blocks
    for (int i = 0; i < NITER; i++)
        iter_kernel<<<grid, 256>>>(i & 1, lam, tau, theta, wx, wy);

    avg_kernel<<<(Ntot + 255)/256, 256>>>(out);
}

// round 4
// speedup vs baseline: 1.3578x; 1.3578x over previous
#include <cuda_runtime.h>

#define Bn 4
#define Hh 512
#define Ww 512
#define HW (Hh*Ww)
#define Ntot (Bn*HW)
#define EPSf 1e-8f
#define NPAIR 10       // 20 iterations = 10 fused pairs
#define T2 28          // owned interior per block (after 2 iters)
#define NT2 19         // ceil(512/28)
#define SPU 33         // s_u pitch (float2)
#define SPP 32         // s_p pitch (float4)

// State in vector-packed device globals (no runtime alloc)
__device__ float4 g_cfg[Ntot];        // (rho_c, gx, gy, pad)
__device__ float2 g_u2[2][Ntot];      // (u0, u1)
__device__ float4 g_p4[2][Ntot];      // (p1x, p1y, p2x, p2y)

__global__ void init_kernel() {
    int i = blockIdx.x*blockDim.x + threadIdx.x;
    if (i < Ntot) {
        g_u2[0][i] = make_float2(0.f, 0.f);
        g_p4[0][i] = make_float4(0.f, 0.f, 0.f, 0.f);
    }
}

// cfg = (I1-I0, K_GRAD_x*I1, K_GRAD_y*I1) with zero padding
__global__ void pre_kernel(const float* __restrict__ x) {
    int i = blockIdx.x*blockDim.x + threadIdx.x;
    if (i >= Ntot) return;
    int b = i >> 18;
    int hw = i & (HW-1);
    int h = hw >> 9;
    int w = hw & (Ww-1);
    const float* I0 = x + (size_t)b*2*HW;
    const float* I1 = I0 + HW;

    auto at = [&](int dh, int dw) -> float {
        int hh = h+dh, ww = w+dw;
        if (hh < 0 || hh >= Hh || ww < 0 || ww >= Ww) return 0.f;
        return I1[hh*Ww + ww];
    };
    float a00=at(-1,-1), a01=at(-1,0), a02=at(-1,1);
    float a10=at( 0,-1),               a12=at( 0,1);
    float a20=at( 1,-1), a21=at( 1,0), a22=at( 1,1);
    float gx = (-a00 + a02 - 2.f*a10 + 2.f*a12 - a20 + a22) * (1.f/6.f);
    float gy = (-a00 - 2.f*a01 - a02 + a20 + 2.f*a21 + a22) * (1.f/6.f);
    g_cfg[i] = make_float4(I1[hw] - I0[hw], gx, gy, 0.f);
}

// TWO fused TV-L1 iterations per launch. Region coords lr,lc in [0,32);
// global pos = block interior origin - 1 + region coord.
//   Phase A: u(1) on 32x32   (global reads: cfg, u_in, p_in +- neighbors)
//   Phase B: p(1) on 31x31   (SMEM u(1); global p_in center)
//   Phase C: u(2) on [1,30)^2 (SMEM u(1) center + p(1) neighbors; global cfg)
//   Phase D: p(2)+writes on [1,29)^2 = 28x28 owned interior
// Out-of-image region points are stored as 0 => exact zero-pad semantics.
__global__ __launch_bounds__(256) void iter2_kernel(int src,
    const float* __restrict__ lam_p, const float* __restrict__ tau_p,
    const float* __restrict__ theta_p,
    const float* __restrict__ wx, const float* __restrict__ wy)
{
    const float theta = theta_p[0];
    const float tl = theta * lam_p[0];
    const float rr = tau_p[0] / theta;
    const float wx0 = wx[0], wx1 = wx[1], wx2 = wx[2];
    const float wy0 = wy[0], wy1 = wy[1], wy2 = wy[2];

    const float2* __restrict__ u_in = g_u2[src];
    const float4* __restrict__ p_in = g_p4[src];
    float2* __restrict__ u_out = g_u2[src^1];
    float4* __restrict__ p_out = g_p4[src^1];

    const int lc = threadIdx.x & 31;
    const int ty = threadIdx.x >> 5;
    const int b  = blockIdx.z;
    const int gh0 = blockIdx.y * T2 - 1;   // region origin (row)
    const int gw0 = blockIdx.x * T2 - 1;   // region origin (col)
    const int gw  = gw0 + lc;
    const int base = b * HW;

    __shared__ float2 s_u[32*SPU];
    __shared__ float4 s_p[31*SPP];

    // ---- Phase A: u(1) on full 32x32 region ----
    #pragma unroll
    for (int i = 0; i < 4; i++) {
        int lr = ty + i*8;
        int gh = gh0 + lr;
        float2 res = make_float2(0.f, 0.f);
        if ((unsigned)gh < Hh && (unsigned)gw < Ww) {
            int idx = base + gh*Ww + gw;
            float4 cfg = g_cfg[idx];
            float2 u = u_in[idx];
            float4 p = p_in[idx];
            float4 z4 = make_float4(0.f, 0.f, 0.f, 0.f);
            float4 pl = (gw > 0)    ? p_in[idx-1]  : z4;
            float4 pr = (gw < Ww-1) ? p_in[idx+1]  : z4;
            float4 pu = (gh > 0)    ? p_in[idx-Ww] : z4;
            float4 pd = (gh < Hh-1) ? p_in[idx+Ww] : z4;
            float gx = cfg.y, gy = cfg.z;
            float rho = cfg.x + gx*u.x + gy*u.y;
            float ng = gx*gx + gy*gy + EPSf;
            float th = tl * ng;
            float d0, d1;
            if (fabsf(rho) < th) {
                float inv = 1.0f / ng;
                d0 = rho*gx*inv; d1 = rho*gy*inv;
            } else {
                float s = (rho > 0.f) ? 1.f : ((rho < 0.f) ? -1.f : 0.f);
                d0 = tl*gx*s; d1 = tl*gy*s;
            }
            float div1 = wx0*pl.x + wx1*p.x + wx2*pr.x + wy0*pu.y + wy1*p.y + wy2*pd.y;
            float div2 = wx0*pl.z + wx1*p.z + wx2*pr.z + wy0*pu.w + wy1*p.w + wy2*pd.w;
            res.x = (u.x - d0) + theta*div1;
            res.y = (u.y - d1) + theta*div2;
        }
        s_u[lr*SPU + lc] = res;
    }
    __syncthreads();

    // ---- Phase B: p(1) on 31x31 region ----
    #pragma unroll
    for (int i = 0; i < 4; i++) {
        int lr = ty + i*8;
        if (lr < 31 && lc < 31) {
            int gh = gh0 + lr;
            float4 res = make_float4(0.f, 0.f, 0.f, 0.f);
            if ((unsigned)gh < Hh && (unsigned)gw < Ww) {
                int idx = base + gh*Ww + gw;
                float4 p = p_in[idx];
                float2 c   = s_u[lr*SPU + lc];
                float2 rgt = s_u[lr*SPU + lc + 1];
                float2 dwn = s_u[(lr+1)*SPU + lc];
                float gx0 = rgt.x - c.x, gy0 = dwn.x - c.x;
                float gx1 = rgt.y - c.y, gy1 = dwn.y - c.y;
                float i1 = 1.f / (1.f + rr*(fabsf(gx0) + fabsf(gy0)));
                float i2 = 1.f / (1.f + rr*(fabsf(gx1) + fabsf(gy1)));
                res = make_float4((p.x + rr*gx0)*i1, (p.y + rr*gy0)*i1,
                                  (p.z + rr*gx1)*i2, (p.w + rr*gy1)*i2);
            }
            s_p[lr*SPP + lc] = res;
        }
    }
    __syncthreads();

    // ---- Phase C: u(2) on [1,30)^2; overwrite s_u in place (center-only read) ----
    #pragma unroll
    for (int i = 0; i < 4; i++) {
        int lr = ty + i*8;
        if (lr >= 1 && lr < 30 && lc >= 1 && lc < 30) {
            int gh = gh0 + lr;
            float2 res = make_float2(0.f, 0.f);
            if ((unsigned)gh < Hh && (unsigned)gw < Ww) {
                int idx = base + gh*Ww + gw;
                float4 cfg = g_cfg[idx];
                float2 u = s_u[lr*SPU + lc];
                float4 p  = s_p[lr*SPP + lc];
                float4 pl = s_p[lr*SPP + lc - 1];
                float4 pr = s_p[lr*SPP + lc + 1];
                float4 pu = s_p[(lr-1)*SPP + lc];
                float4 pd = s_p[(lr+1)*SPP + lc];
                float gx = cfg.y, gy = cfg.z;
                float rho = cfg.x + gx*u.x + gy*u.y;
                float ng = gx*gx + gy*gy + EPSf;
                float th = tl * ng;
                float d0, d1;
                if (fabsf(rho) < th) {
                    float inv = 1.0f / ng;
                    d0 = rho*gx*inv; d1 = rho*gy*inv;
                } else {
                    float s = (rho > 0.f) ? 1.f : ((rho < 0.f) ? -1.f : 0.f);
                    d0 = tl*gx*s; d1 = tl*gy*s;
                }
                float div1 = wx0*pl.x + wx1*p.x + wx2*pr.x + wy0*pu.y + wy1*p.y + wy2*pd.y;
                float div2 = wx0*pl.z + wx1*p.z + wx2*pr.z + wy0*pu.w + wy1*p.w + wy2*pd.w;
                res.x = (u.x - d0) + theta*div1;
                res.y = (u.y - d1) + theta*div2;
            }
            s_u[lr*SPU + lc] = res;
        }
    }
    __syncthreads();

    // ---- Phase D: p(2) + global writes on the 28x28 owned interior ----
    #pragma unroll
    for (int i = 0; i < 4; i++) {
        int lr = ty + i*8;
        if (lr >= 1 && lr < 29 && lc >= 1 && lc < 29) {
            int gh = gh0 + lr;
            if ((unsigned)gh < Hh && (unsigned)gw < Ww) {
                int idx = base + gh*Ww + gw;
                float4 p   = s_p[lr*SPP + lc];
                float2 c   = s_u[lr*SPU + lc];
                float2 rgt = s_u[lr*SPU + lc + 1];
                float2 dwn = s_u[(lr+1)*SPU + lc];
                float gx0 = rgt.x - c.x, gy0 = dwn.x - c.x;
                float gx1 = rgt.y - c.y, gy1 = dwn.y - c.y;
                float i1 = 1.f / (1.f + rr*(fabsf(gx0) + fabsf(gy0)));
                float i2 = 1.f / (1.f + rr*(fabsf(gx1) + fabsf(gy1)));
                u_out[idx] = c;
                p_out[idx] = make_float4((p.x + rr*gx0)*i1,
                                         (p.y + rr*gy0)*i1,
                                         (p.z + rr*gx1)*i2,
                                         (p.w + rr*gy1)*i2);
            }
        }
    }
}

// AvgPool2d(3, stride 1, pad 1, count_include_pad -> always /9), both channels
__global__ void avg_kernel(float* __restrict__ out) {
    int i = blockIdx.x*blockDim.x + threadIdx.x;
    if (i >= Ntot) return;
    int w = i & (Ww-1);
    int h = (i >> 9) & (Hh-1);
    int b = i >> 18;
    const float2* u = g_u2[0] + b*HW;   // final state is in buf 0 after 10 pairs
    float sx = 0.f, sy = 0.f;
    #pragma unroll
    for (int dh = -1; dh <= 1; dh++) {
        int hh = h + dh;
        if (hh < 0 || hh >= Hh) continue;
        #pragma unroll
        for (int dw = -1; dw <= 1; dw++) {
            int ww = w + dw;
            if (ww < 0 || ww >= Ww) continue;
            float2 v = u[hh*Ww + ww];
            sx += v.x; sy += v.y;
        }
    }
    int o = b*2*HW + h*Ww + w;
    out[o]      = sx * (1.f/9.f);
    out[o + HW] = sy * (1.f/9.f);
}

extern "C" void kernel_launch(void* const* d_in, const int* in_sizes, int n_in,
                              void* d_out, int out_size) {
    const float* x     = (const float*)d_in[0];
    const float* lam   = (const float*)d_in[1];
    const float* tau   = (const float*)d_in[2];
    const float* theta = (const float*)d_in[3];
    const float* wx    = (const float*)d_in[4];
    const float* wy    = (const float*)d_in[5];
    float* out = (float*)d_out;

    init_kernel<<<(Ntot + 255)/256, 256>>>();
    pre_kernel<<<(Ntot + 255)/256, 256>>>(x);

    dim3 grid(NT2, NT2, Bn);   // 19 x 19 x 4 = 1444 blocks
    for (int i = 0; i < NPAIR; i++)
        iter2_kernel<<<grid, 256>>>(i & 1, lam, tau, theta, wx, wy);

    avg_kernel<<<(Ntot + 255)/256, 256>>>(out);
}

// round 5
// speedup vs baseline: 1.8554x; 1.3665x over previous
#include <cuda_runtime.h>

#define Bn 4
#define Hh 512
#define Ww 512
#define HW (Hh*Ww)
#define Ntot (Bn*HW)
#define EPSf 1e-8f
#define NPAIR 10       // 20 iterations = 10 fused pairs
#define T2 28          // owned interior per block (after 2 iters)
#define NT2 19         // ceil(512/28)
#define SPU 33         // s_u pitch (float2)
#define SPP 33         // s_pa/s_pb pitch (float2)

// State in vector-packed device globals (no runtime alloc).
// p split by access direction: pa=(p1x,p2x) read at w+-1, pb=(p1y,p2y) read at h+-1.
__device__ float4 g_cfg[Ntot];        // (rho_c, gx, gy, pad)
__device__ float2 g_u2[2][Ntot];
__device__ float2 g_pa[2][Ntot];
__device__ float2 g_pb[2][Ntot];

// init state + cfg = (I1-I0, K_GRAD_x*I1, K_GRAD_y*I1), zero padding
__global__ void pre_kernel(const float* __restrict__ x) {
    int i = blockIdx.x*blockDim.x + threadIdx.x;
    if (i >= Ntot) return;
    float2 z2 = make_float2(0.f, 0.f);
    g_u2[0][i] = z2; g_pa[0][i] = z2; g_pb[0][i] = z2;

    int b = i >> 18;
    int hw = i & (HW-1);
    int h = hw >> 9;
    int w = hw & (Ww-1);
    const float* I0 = x + (size_t)b*2*HW;
    const float* I1 = I0 + HW;

    auto at = [&](int dh, int dw) -> float {
        int hh = h+dh, ww = w+dw;
        if (hh < 0 || hh >= Hh || ww < 0 || ww >= Ww) return 0.f;
        return I1[hh*Ww + ww];
    };
    float a00=at(-1,-1), a01=at(-1,0), a02=at(-1,1);
    float a10=at( 0,-1),               a12=at( 0,1);
    float a20=at( 1,-1), a21=at( 1,0), a22=at( 1,1);
    float gx = (-a00 + a02 - 2.f*a10 + 2.f*a12 - a20 + a22) * (1.f/6.f);
    float gy = (-a00 - 2.f*a01 - a02 + a20 + 2.f*a21 + a22) * (1.f/6.f);
    g_cfg[i] = make_float4(I1[hw] - I0[hw], gx, gy, 0.f);
}

// TWO fused TV-L1 iterations per launch (phases A-D, see R4 notes).
// Out-of-image region points are stored as 0 => exact zero-pad semantics.
__global__ __launch_bounds__(256) void iter2_kernel(int src, int last,
    const float* __restrict__ lam_p, const float* __restrict__ tau_p,
    const float* __restrict__ theta_p,
    const float* __restrict__ wx, const float* __restrict__ wy)
{
    const float theta = theta_p[0];
    const float tl = theta * lam_p[0];
    const float rr = tau_p[0] / theta;
    const float wx0 = wx[0], wx1 = wx[1], wx2 = wx[2];
    const float wy0 = wy[0], wy1 = wy[1], wy2 = wy[2];

    const float2* __restrict__ u_in  = g_u2[src];
    const float2* __restrict__ pa_in = g_pa[src];
    const float2* __restrict__ pb_in = g_pb[src];
    float2* __restrict__ u_out  = g_u2[src^1];
    float2* __restrict__ pa_out = g_pa[src^1];
    float2* __restrict__ pb_out = g_pb[src^1];

    const int lc = threadIdx.x & 31;
    const int ty = threadIdx.x >> 5;
    const int b  = blockIdx.z;
    const int gh0 = blockIdx.y * T2 - 1;   // region origin (row)
    const int gw0 = blockIdx.x * T2 - 1;   // region origin (col)
    const int gw  = gw0 + lc;
    const int base = b * HW;

    __shared__ float2 s_u [32*SPU];
    __shared__ float2 s_pa[31*SPP];
    __shared__ float2 s_pb[31*SPP];

    // ---- Phase A: u(1) on full 32x32 region ----
    #pragma unroll
    for (int i = 0; i < 4; i++) {
        int lr = ty + i*8;
        int gh = gh0 + lr;
        float2 res = make_float2(0.f, 0.f);
        if ((unsigned)gh < Hh && (unsigned)gw < Ww) {
            int idx = base + gh*Ww + gw;
            float4 cfg = g_cfg[idx];
            float2 u  = u_in[idx];
            float2 pa = pa_in[idx];
            float2 pb = pb_in[idx];
            float2 z2 = make_float2(0.f, 0.f);
            float2 pl = (gw > 0)    ? pa_in[idx-1]  : z2;
            float2 pr = (gw < Ww-1) ? pa_in[idx+1]  : z2;
            float2 pu = (gh > 0)    ? pb_in[idx-Ww] : z2;
            float2 pd = (gh < Hh-1) ? pb_in[idx+Ww] : z2;
            float gx = cfg.y, gy = cfg.z;
            float rho = cfg.x + gx*u.x + gy*u.y;
            float ng = gx*gx + gy*gy + EPSf;
            float th = tl * ng;
            float d0, d1;
            if (fabsf(rho) < th) {
                float inv = 1.0f / ng;
                d0 = rho*gx*inv; d1 = rho*gy*inv;
            } else {
                float s = (rho > 0.f) ? 1.f : ((rho < 0.f) ? -1.f : 0.f);
                d0 = tl*gx*s; d1 = tl*gy*s;
            }
            float div1 = wx0*pl.x + wx1*pa.x + wx2*pr.x + wy0*pu.x + wy1*pb.x + wy2*pd.x;
            float div2 = wx0*pl.y + wx1*pa.y + wx2*pr.y + wy0*pu.y + wy1*pb.y + wy2*pd.y;
            res.x = (u.x - d0) + theta*div1;
            res.y = (u.y - d1) + theta*div2;
        }
        s_u[lr*SPU + lc] = res;
    }
    __syncthreads();

    // ---- Phase B: p(1) on 31x31 region ----
    #pragma unroll
    for (int i = 0; i < 4; i++) {
        int lr = ty + i*8;
        if (lr < 31 && lc < 31) {
            int gh = gh0 + lr;
            float2 ra = make_float2(0.f, 0.f), rb = make_float2(0.f, 0.f);
            if ((unsigned)gh < Hh && (unsigned)gw < Ww) {
                int idx = base + gh*Ww + gw;
                float2 pa = pa_in[idx];
                float2 pb = pb_in[idx];
                float2 c   = s_u[lr*SPU + lc];
                float2 rgt = s_u[lr*SPU + lc + 1];
                float2 dwn = s_u[(lr+1)*SPU + lc];
                float gx0 = rgt.x - c.x, gy0 = dwn.x - c.x;
                float gx1 = rgt.y - c.y, gy1 = dwn.y - c.y;
                float i1 = 1.f / (1.f + rr*(fabsf(gx0) + fabsf(gy0)));
                float i2 = 1.f / (1.f + rr*(fabsf(gx1) + fabsf(gy1)));
                ra = make_float2((pa.x + rr*gx0)*i1, (pa.y + rr*gx1)*i2);
                rb = make_float2((pb.x + rr*gy0)*i1, (pb.y + rr*gy1)*i2);
            }
            s_pa[lr*SPP + lc] = ra;
            s_pb[lr*SPP + lc] = rb;
        }
    }
    __syncthreads();

    // ---- Phase C: u(2) on [1,30)^2; overwrite s_u in place (center-only read) ----
    #pragma unroll
    for (int i = 0; i < 4; i++) {
        int lr = ty + i*8;
        if (lr >= 1 && lr < 30 && lc >= 1 && lc < 30) {
            int gh = gh0 + lr;
            float2 res = make_float2(0.f, 0.f);
            if ((unsigned)gh < Hh && (unsigned)gw < Ww) {
                int idx = base + gh*Ww + gw;
                float4 cfg = g_cfg[idx];
                float2 u  = s_u[lr*SPU + lc];
                float2 pa = s_pa[lr*SPP + lc];
                float2 pb = s_pb[lr*SPP + lc];
                float2 pl = s_pa[lr*SPP + lc - 1];
                float2 pr = s_pa[lr*SPP + lc + 1];
                float2 pu = s_pb[(lr-1)*SPP + lc];
                float2 pd = s_pb[(lr+1)*SPP + lc];
                float gx = cfg.y, gy = cfg.z;
                float rho = cfg.x + gx*u.x + gy*u.y;
                float ng = gx*gx + gy*gy + EPSf;
                float th = tl * ng;
                float d0, d1;
                if (fabsf(rho) < th) {
                    float inv = 1.0f / ng;
                    d0 = rho*gx*inv; d1 = rho*gy*inv;
                } else {
                    float s = (rho > 0.f) ? 1.f : ((rho < 0.f) ? -1.f : 0.f);
                    d0 = tl*gx*s; d1 = tl*gy*s;
                }
                float div1 = wx0*pl.x + wx1*pa.x + wx2*pr.x + wy0*pu.x + wy1*pb.x + wy2*pd.x;
                float div2 = wx0*pl.y + wx1*pa.y + wx2*pr.y + wy0*pu.y + wy1*pb.y + wy2*pd.y;
                res.x = (u.x - d0) + theta*div1;
                res.y = (u.y - d1) + theta*div2;
            }
            s_u[lr*SPU + lc] = res;
        }
    }
    __syncthreads();

    // ---- Phase D: p(2) + global writes on the 28x28 owned interior ----
    #pragma unroll
    for (int i = 0; i < 4; i++) {
        int lr = ty + i*8;
        if (lr >= 1 && lr < 29 && lc >= 1 && lc < 29) {
            int gh = gh0 + lr;
            if ((unsigned)gh < Hh && (unsigned)gw < Ww) {
                int idx = base + gh*Ww + gw;
                float2 c = s_u[lr*SPU + lc];
                u_out[idx] = c;
                if (!last) {
                    float2 pa  = s_pa[lr*SPP + lc];
                    float2 pb  = s_pb[lr*SPP + lc];
                    float2 rgt = s_u[lr*SPU + lc + 1];
                    float2 dwn = s_u[(lr+1)*SPU + lc];
                    float gx0 = rgt.x - c.x, gy0 = dwn.x - c.x;
                    float gx1 = rgt.y - c.y, gy1 = dwn.y - c.y;
                    float i1 = 1.f / (1.f + rr*(fabsf(gx0) + fabsf(gy0)));
                    float i2 = 1.f / (1.f + rr*(fabsf(gx1) + fabsf(gy1)));
                    pa_out[idx] = make_float2((pa.x + rr*gx0)*i1, (pa.y + rr*gx1)*i2);
                    pb_out[idx] = make_float2((pb.x + rr*gy0)*i1, (pb.y + rr*gy1)*i2);
                }
            }
        }
    }
}

// AvgPool2d(3, stride 1, pad 1, count_include_pad -> always /9), both channels
__global__ void avg_kernel(float* __restrict__ out) {
    int i = blockIdx.x*blockDim.x + threadIdx.x;
    if (i >= Ntot) return;
    int w = i & (Ww-1);
    int h = (i >> 9) & (Hh-1);
    int b = i >> 18;
    const float2* u = g_u2[0] + b*HW;   // final state is in buf 0 after 10 pairs
    float sx = 0.f, sy = 0.f;
    #pragma unroll
    for (int dh = -1; dh <= 1; dh++) {
        int hh = h + dh;
        if (hh < 0 || hh >= Hh) continue;
        #pragma unroll
        for (int dw = -1; dw <= 1; dw++) {
            int ww = w + dw;
            if (ww < 0 || ww >= Ww) continue;
            float2 v = u[hh*Ww + ww];
            sx += v.x; sy += v.y;
        }
    }
    int o = b*2*HW + h*Ww + w;
    out[o]      = sx * (1.f/9.f);
    out[o + HW] = sy * (1.f/9.f);
}

extern "C" void kernel_launch(void* const* d_in, const int* in_sizes, int n_in,
                              void* d_out, int out_size) {
    const float* x     = (const float*)d_in[0];
    const float* lam   = (const float*)d_in[1];
    const float* tau   = (const float*)d_in[2];
    const float* theta = (const float*)d_in[3];
    const float* wx    = (const float*)d_in[4];
    const float* wy    = (const float*)d_in[5];
    float* out = (float*)d_out;

    pre_kernel<<<(Ntot + 255)/256, 256>>>(x);

    dim3 grid(NT2, NT2, Bn);   // 19 x 19 x 4 = 1444 blocks
    for (int i = 0; i < NPAIR; i++)
        iter2_kernel<<<grid, 256>>>(i & 1, i == NPAIR-1, lam, tau, theta, wx, wy);

    avg_kernel<<<(Ntot + 255)/256, 256>>>(out);
}